// round 1
// baseline (speedup 1.0000x reference)
#include <cuda_runtime.h>
#include <math.h>

#define DMODEL 1024
#define SEQ    2048
#define NB     2
#define NH     16
#define HD     64
#define MTOT   (NB*SEQ)          // 4096
#define ATT_SCALE 0.125f         // 64^-0.5

// Scratch (allocation-free rule: __device__ globals)
__device__ __align__(16) float g_q[MTOT*DMODEL];
__device__ __align__(16) float g_k[MTOT*DMODEL];
__device__ __align__(16) float g_v[MTOT*DMODEL];
__device__ __align__(16) float g_attn[MTOT*DMODEL];

// ---------------------------------------------------------------------------
// C[M,N] = A[M,1024] @ W[N,1024]^T, optional fused RoPE epilogue.
// 64x64 tile, BK=16, 128 threads, each thread 4 rows x 8 cols
// (cols = {4tx..4tx+3} and {32+4tx..32+4tx+3} so RoPE pairs are in-thread).
// ---------------------------------------------------------------------------
__global__ __launch_bounds__(128)
void gemm_nt_kernel(const float* __restrict__ A, const float* __restrict__ W,
                    float* __restrict__ C, int doRope)
{
    __shared__ __align__(16) float As[16*68];   // [k][m], stride 68
    __shared__ __align__(16) float Bs[16*68];   // [k][n], stride 68

    const int tid = threadIdx.x;
    const int tx  = tid & 7;          // 0..7
    const int ty  = tid >> 3;         // 0..15
    const int m0  = blockIdx.y << 6;
    const int n0  = blockIdx.x << 6;

    const int lr = tid >> 2;          // 0..31
    const int lc = (tid & 3) << 2;    // 0,4,8,12

    float acc[4][8];
#pragma unroll
    for (int i = 0; i < 4; ++i)
#pragma unroll
        for (int j = 0; j < 8; ++j) acc[i][j] = 0.f;

    const float* Arow0 = A + (size_t)(m0 + lr)      * DMODEL + lc;
    const float* Arow1 = A + (size_t)(m0 + lr + 32) * DMODEL + lc;
    const float* Wrow0 = W + (size_t)(n0 + lr)      * DMODEL + lc;
    const float* Wrow1 = W + (size_t)(n0 + lr + 32) * DMODEL + lc;

    for (int k0 = 0; k0 < DMODEL; k0 += 16) {
        float4 a0 = *(const float4*)(Arow0 + k0);
        float4 a1 = *(const float4*)(Arow1 + k0);
        float4 b0 = *(const float4*)(Wrow0 + k0);
        float4 b1 = *(const float4*)(Wrow1 + k0);

        __syncthreads();
        As[(lc+0)*68 + lr]      = a0.x;
        As[(lc+1)*68 + lr]      = a0.y;
        As[(lc+2)*68 + lr]      = a0.z;
        As[(lc+3)*68 + lr]      = a0.w;
        As[(lc+0)*68 + lr + 32] = a1.x;
        As[(lc+1)*68 + lr + 32] = a1.y;
        As[(lc+2)*68 + lr + 32] = a1.z;
        As[(lc+3)*68 + lr + 32] = a1.w;
        Bs[(lc+0)*68 + lr]      = b0.x;
        Bs[(lc+1)*68 + lr]      = b0.y;
        Bs[(lc+2)*68 + lr]      = b0.z;
        Bs[(lc+3)*68 + lr]      = b0.w;
        Bs[(lc+0)*68 + lr + 32] = b1.x;
        Bs[(lc+1)*68 + lr + 32] = b1.y;
        Bs[(lc+2)*68 + lr + 32] = b1.z;
        Bs[(lc+3)*68 + lr + 32] = b1.w;
        __syncthreads();

#pragma unroll
        for (int k = 0; k < 16; ++k) {
            float4 av  = *(const float4*)(As + k*68 + ty*4);
            float4 bv0 = *(const float4*)(Bs + k*68 + tx*4);
            float4 bv1 = *(const float4*)(Bs + k*68 + 32 + tx*4);
            float a[4] = {av.x, av.y, av.z, av.w};
            float b[8] = {bv0.x, bv0.y, bv0.z, bv0.w, bv1.x, bv1.y, bv1.z, bv1.w};
#pragma unroll
            for (int i = 0; i < 4; ++i)
#pragma unroll
                for (int j = 0; j < 8; ++j)
                    acc[i][j] = fmaf(a[i], b[j], acc[i][j]);
        }
    }

    if (doRope) {
#pragma unroll
        for (int jj = 0; jj < 4; ++jj) {
            int d1 = tx*4 + jj;                              // 0..31
            float invf = (float)pow(10000.0, -(double)(2*d1)/64.0);
#pragma unroll
            for (int i = 0; i < 4; ++i) {
                int row = m0 + ty*4 + i;
                int t   = row & (SEQ - 1);
                float th = (float)t * invf;
                float sn, cs;
                sincosf(th, &sn, &cs);
                float v1 = acc[i][jj];
                float v2 = acc[i][jj+4];
                C[(size_t)row*DMODEL + n0 + d1]      = v1*cs - v2*sn;
                C[(size_t)row*DMODEL + n0 + d1 + 32] = v2*cs + v1*sn;
            }
        }
    } else {
#pragma unroll
        for (int i = 0; i < 4; ++i) {
            int row = m0 + ty*4 + i;
#pragma unroll
            for (int jj = 0; jj < 4; ++jj) {
                C[(size_t)row*DMODEL + n0 + tx*4 + jj]      = acc[i][jj];
                C[(size_t)row*DMODEL + n0 + tx*4 + jj + 32] = acc[i][jj+4];
            }
        }
    }
}

// ---------------------------------------------------------------------------
// Flash attention, causal, Dh=64. One CTA = 64 query rows of one (b,h).
// 256 threads (16x16), each thread 4 rows x 4 cols.
// smem layouts (stride 68):
//   Qs[d][r], Ks[d][j]  -> GEMM1 operands both read as float4
//   Ps[j][r], Vs[j][d]  -> GEMM2 operands both read as float4
// ---------------------------------------------------------------------------
#define ASTR 68
__global__ __launch_bounds__(256)
void attn_kernel()
{
    extern __shared__ __align__(16) float sm[];
    float* Qs = sm;
    float* Ks = sm + 64*ASTR;
    float* Vs = sm + 2*64*ASTR;
    float* Ps = sm + 3*64*ASTR;

    const int tid = threadIdx.x;
    const int tx  = tid & 15;
    const int ty  = tid >> 4;
    const int it  = blockIdx.x;
    const int h   = blockIdx.y;
    const int b   = blockIdx.z;
    const int i0  = it << 6;

    // ---- load Q tile (transposed into Qs[d][r]) ----
    {
        int r  = tid >> 2;             // 0..63
        int c0 = (tid & 3) << 4;       // 0,16,32,48
        const float* qp = g_q + (size_t)(b*SEQ + i0 + r)*DMODEL + h*HD + c0;
#pragma unroll
        for (int u = 0; u < 4; ++u) {
            float4 v = *(const float4*)(qp + u*4);
            Qs[(c0 + u*4 + 0)*ASTR + r] = v.x;
            Qs[(c0 + u*4 + 1)*ASTR + r] = v.y;
            Qs[(c0 + u*4 + 2)*ASTR + r] = v.z;
            Qs[(c0 + u*4 + 3)*ASTR + r] = v.w;
        }
    }

    float m[4], l[4], o[4][4];
#pragma unroll
    for (int i = 0; i < 4; ++i) {
        m[i] = -3.0e38f;
        l[i] = 0.f;
#pragma unroll
        for (int j = 0; j < 4; ++j) o[i][j] = 0.f;
    }

    for (int jt = 0; jt <= it; ++jt) {
        const int j0 = jt << 6;

        // prefetch K,V tile into registers
        int r  = tid >> 2;
        int c0 = (tid & 3) << 4;
        const float* kp = g_k + (size_t)(b*SEQ + j0 + r)*DMODEL + h*HD + c0;
        const float* vp = g_v + (size_t)(b*SEQ + j0 + r)*DMODEL + h*HD + c0;
        float4 kv[4], vv[4];
#pragma unroll
        for (int u = 0; u < 4; ++u) {
            kv[u] = *(const float4*)(kp + u*4);
            vv[u] = *(const float4*)(vp + u*4);
        }

        __syncthreads();   // previous iteration's GEMMs done
#pragma unroll
        for (int u = 0; u < 4; ++u) {
            Ks[(c0 + u*4 + 0)*ASTR + r] = kv[u].x;
            Ks[(c0 + u*4 + 1)*ASTR + r] = kv[u].y;
            Ks[(c0 + u*4 + 2)*ASTR + r] = kv[u].z;
            Ks[(c0 + u*4 + 3)*ASTR + r] = kv[u].w;
            *(float4*)(Vs + r*ASTR + c0 + u*4) = vv[u];
        }
        __syncthreads();   // tiles ready

        // GEMM1: s = Q K^T
        float s[4][4];
#pragma unroll
        for (int i = 0; i < 4; ++i)
#pragma unroll
            for (int j = 0; j < 4; ++j) s[i][j] = 0.f;
#pragma unroll
        for (int k = 0; k < 64; ++k) {
            float4 a = *(const float4*)(Qs + k*ASTR + ty*4);
            float4 bq = *(const float4*)(Ks + k*ASTR + tx*4);
            float aa[4] = {a.x, a.y, a.z, a.w};
            float bb[4] = {bq.x, bq.y, bq.z, bq.w};
#pragma unroll
            for (int i = 0; i < 4; ++i)
#pragma unroll
                for (int j = 0; j < 4; ++j)
                    s[i][j] = fmaf(aa[i], bb[j], s[i][j]);
        }
#pragma unroll
        for (int i = 0; i < 4; ++i)
#pragma unroll
            for (int j = 0; j < 4; ++j) s[i][j] *= ATT_SCALE;

        if (jt == it) {   // causal mask on diagonal tile
#pragma unroll
            for (int i = 0; i < 4; ++i)
#pragma unroll
                for (int j = 0; j < 4; ++j)
                    if (j0 + tx*4 + j > i0 + ty*4 + i) s[i][j] = -1.0e30f;
        }

        // online softmax update
        float p[4][4];
#pragma unroll
        for (int i = 0; i < 4; ++i) {
            float tm = fmaxf(fmaxf(s[i][0], s[i][1]), fmaxf(s[i][2], s[i][3]));
#pragma unroll
            for (int off = 8; off >= 1; off >>= 1)
                tm = fmaxf(tm, __shfl_xor_sync(0xffffffffu, tm, off));
            float mnew = fmaxf(m[i], tm);
            float corr = expf(m[i] - mnew);
            float rs = 0.f;
#pragma unroll
            for (int j = 0; j < 4; ++j) {
                float e = expf(s[i][j] - mnew);
                p[i][j] = e;
                rs += e;
            }
#pragma unroll
            for (int off = 8; off >= 1; off >>= 1)
                rs += __shfl_xor_sync(0xffffffffu, rs, off);
            l[i] = l[i]*corr + rs;
            m[i] = mnew;
#pragma unroll
            for (int d = 0; d < 4; ++d) o[i][d] *= corr;
        }

        // store P transposed: Ps[j][r]
#pragma unroll
        for (int j = 0; j < 4; ++j)
#pragma unroll
            for (int i = 0; i < 4; ++i)
                Ps[(tx*4 + j)*ASTR + ty*4 + i] = p[i][j];
        __syncthreads();   // Ps ready

        // GEMM2: o += P V
#pragma unroll
        for (int k = 0; k < 64; ++k) {
            float4 a  = *(const float4*)(Ps + k*ASTR + ty*4);
            float4 bv = *(const float4*)(Vs + k*ASTR + tx*4);
            float aa[4] = {a.x, a.y, a.z, a.w};
            float bb[4] = {bv.x, bv.y, bv.z, bv.w};
#pragma unroll
            for (int i = 0; i < 4; ++i)
#pragma unroll
                for (int d = 0; d < 4; ++d)
                    o[i][d] = fmaf(aa[i], bb[d], o[i][d]);
        }
    }

    // normalize + write
#pragma unroll
    for (int i = 0; i < 4; ++i) {
        float inv = 1.f / l[i];
        int row = i0 + ty*4 + i;
        float4 w = make_float4(o[i][0]*inv, o[i][1]*inv, o[i][2]*inv, o[i][3]*inv);
        *(float4*)(g_attn + (size_t)(b*SEQ + row)*DMODEL + h*HD + tx*4) = w;
    }
}

// ---------------------------------------------------------------------------
extern "C" void kernel_launch(void* const* d_in, const int* in_sizes, int n_in,
                              void* d_out, int out_size)
{
    const float* x  = (const float*)d_in[0];
    const float* wq = (const float*)d_in[1];
    const float* wk = (const float*)d_in[2];
    const float* wv = (const float*)d_in[3];
    const float* wo = (const float*)d_in[4];
    // d_in[5] = attention_mask (tril) — causal handled analytically.
    float* out = (float*)d_out;

    float *q, *k, *v, *attn;
    cudaGetSymbolAddress((void**)&q,    g_q);
    cudaGetSymbolAddress((void**)&k,    g_k);
    cudaGetSymbolAddress((void**)&v,    g_v);
    cudaGetSymbolAddress((void**)&attn, g_attn);

    dim3 gb(DMODEL/64, MTOT/64);     // (16, 64)
    gemm_nt_kernel<<<gb, 128>>>(x, wq, q, 1);
    gemm_nt_kernel<<<gb, 128>>>(x, wk, k, 1);
    gemm_nt_kernel<<<gb, 128>>>(x, wv, v, 0);

    size_t shm = (size_t)4 * 64 * ASTR * sizeof(float);   // 69632 B
    cudaFuncSetAttribute(attn_kernel,
                         cudaFuncAttributeMaxDynamicSharedMemorySize, (int)shm);
    attn_kernel<<<dim3(SEQ/64, NH, NB), 256, shm>>>();

    gemm_nt_kernel<<<gb, 128>>>(attn, wo, out, 0);
}

// round 3
// speedup vs baseline: 1.4878x; 1.4878x over previous
#include <cuda_runtime.h>
#include <cuda_bf16.h>
#include <math.h>
#include <stdint.h>

#define DMODEL 1024
#define SEQ    2048
#define NB     2
#define NH     16
#define HD     64
#define MTOT   (NB*SEQ)          // 4096
#define ATT_SCALE 0.125f

// ---------------- scratch (__device__ globals; allocation-free rule) --------
__device__ __align__(16) float g_q[MTOT*DMODEL];
__device__ __align__(16) float g_k[MTOT*DMODEL];
__device__ __align__(16) float g_v[MTOT*DMODEL];
__device__ __align__(16) float g_attn[MTOT*DMODEL];
__device__ __align__(16) __nv_bfloat16 g_xs1[MTOT*DMODEL];
__device__ __align__(16) __nv_bfloat16 g_xs2[MTOT*DMODEL];
__device__ __align__(16) __nv_bfloat16 g_as1[MTOT*DMODEL];
__device__ __align__(16) __nv_bfloat16 g_as2[MTOT*DMODEL];
__device__ __align__(16) __nv_bfloat16 g_w1[4*DMODEL*DMODEL];
__device__ __align__(16) __nv_bfloat16 g_w2[4*DMODEL*DMODEL];

// ---------------- PTX helpers ----------------------------------------------
__device__ __forceinline__ uint32_t smem_u32(const void* p) {
    uint32_t a;
    asm("{ .reg .u64 t; cvta.to.shared.u64 t, %1; cvt.u32.u64 %0, t; }"
        : "=r"(a) : "l"(p));
    return a;
}
__device__ __forceinline__ void cp16(uint32_t dst, const void* src) {
    asm volatile("cp.async.cg.shared.global [%0], [%1], 16;" :: "r"(dst), "l"(src));
}
#define CP_COMMIT()  asm volatile("cp.async.commit_group;" ::: "memory")
#define CP_WAIT(n)   asm volatile("cp.async.wait_group %0;" :: "n"(n) : "memory")

#define LDSM4(r, adr) \
    asm volatile("ldmatrix.sync.aligned.m8n8.x4.shared.b16 {%0,%1,%2,%3}, [%4];" \
        : "=r"((r)[0]), "=r"((r)[1]), "=r"((r)[2]), "=r"((r)[3]) : "r"(adr))

#define MMA_BF16(c, a, b) \
    asm volatile("mma.sync.aligned.m16n8k16.row.col.f32.bf16.bf16.f32 " \
        "{%0,%1,%2,%3}, {%4,%5,%6,%7}, {%8,%9}, {%0,%1,%2,%3};" \
        : "+f"((c)[0]), "+f"((c)[1]), "+f"((c)[2]), "+f"((c)[3]) \
        : "r"((a)[0]), "r"((a)[1]), "r"((a)[2]), "r"((a)[3]), \
          "r"((b)[0]), "r"((b)[1]))

// ---------------- split kernel: fp32 -> bf16 hi + bf16 lo -------------------
__global__ __launch_bounds__(256)
void split_kernel(const float* __restrict__ s, __nv_bfloat16* __restrict__ d1,
                  __nv_bfloat16* __restrict__ d2, int n4)
{
    int i = blockIdx.x * blockDim.x + threadIdx.x;
    if (i >= n4) return;
    float4 v = ((const float4*)s)[i];
    float a[4] = {v.x, v.y, v.z, v.w};
    uint32_t h[4], l[4];
#pragma unroll
    for (int j = 0; j < 4; ++j) {
        __nv_bfloat16 hi = __float2bfloat16(a[j]);
        __nv_bfloat16 lo = __float2bfloat16(a[j] - __bfloat162float(hi));
        h[j] = __bfloat16_as_ushort(hi);
        l[j] = __bfloat16_as_ushort(lo);
    }
    uint2 ph = make_uint2((h[1] << 16) | h[0], (h[3] << 16) | h[2]);
    uint2 pl = make_uint2((l[1] << 16) | l[0], (l[3] << 16) | l[2]);
    ((uint2*)d1)[i] = ph;
    ((uint2*)d2)[i] = pl;
}

// ---------------- mma.sync GEMM: C[M,1024] = A @ W^T, fused RoPE ------------
// CTA tile 128x128, BK=32, 8 warps (4M x 2N), warp tile 32x64.
// 3-term split: C = A1*B1 + A1*B2 + A2*B1 (fp32 accumulate).
// smem tiles: [128][40] bf16 (stride 40 => conflict-free ldmatrix).
#define TILE_BYTES 10240            // 128*40*2
#define STAGE_BYTES (4*TILE_BYTES)  // A1,A2,B1,B2

__global__ __launch_bounds__(256)
void gemm_mma(const __nv_bfloat16* __restrict__ A1, const __nv_bfloat16* __restrict__ A2,
              const __nv_bfloat16* __restrict__ B1, const __nv_bfloat16* __restrict__ B2,
              float* __restrict__ C, int doRope)
{
    extern __shared__ __align__(16) char sm[];
    const uint32_t sb = smem_u32(sm);
    const int tid = threadIdx.x;
    const int lane = tid & 31, wid = tid >> 5;
    const int wm = wid & 3, wn = wid >> 2;        // 4 x 2 warp grid
    const int m0 = blockIdx.y << 7, n0 = blockIdx.x << 7;

    float acc[2][8][4];
#pragma unroll
    for (int mf = 0; mf < 2; ++mf)
#pragma unroll
        for (int nf = 0; nf < 8; ++nf)
#pragma unroll
            for (int j = 0; j < 4; ++j) acc[mf][nf][j] = 0.f;

    // per-thread load coords (8 x 16B per stage)
    const int lrow0 = tid >> 2;        // rows  0..63  (u=0)
    const int lch   = tid & 3;         // 16B chunk 0..3

    auto load_stage = [&](int t) {
        const int k0 = t << 5;
        const uint32_t base = sb + (uint32_t)(t & 1) * STAGE_BYTES;
#pragma unroll
        for (int tile = 0; tile < 4; ++tile) {
            const __nv_bfloat16* S = (tile == 0) ? A1 : (tile == 1) ? A2
                                   : (tile == 2) ? B1 : B2;
            const int rb = (tile < 2) ? m0 : n0;
#pragma unroll
            for (int u = 0; u < 2; ++u) {
                int row = lrow0 + (u << 6);
                cp16(base + tile * TILE_BYTES + row * 80 + lch * 16,
                     S + (size_t)(rb + row) * DMODEL + k0 + lch * 8);
            }
        }
    };

    load_stage(0);
    CP_COMMIT();

    // ldmatrix per-lane offsets
    const uint32_t a_roff = (uint32_t)(lane & 15) * 80;
    const uint32_t a_koff = (uint32_t)(lane >> 4) * 16;       // bytes
    const int      b_nloc = (lane & 7) + ((lane >> 4) & 1) * 8;
    const uint32_t b_koff = (uint32_t)((lane >> 3) & 1) * 16; // bytes

    for (int t = 0; t < 32; ++t) {
        if (t < 31) {
            load_stage(t + 1);
            CP_COMMIT();
            CP_WAIT(1);
        } else {
            CP_WAIT(0);
        }
        __syncthreads();

        const uint32_t buf = sb + (uint32_t)(t & 1) * STAGE_BYTES;
#pragma unroll
        for (int ks = 0; ks < 2; ++ks) {
            const uint32_t kbyte = (uint32_t)ks * 32;
            uint32_t A1f[2][4], A2f[2][4];
#pragma unroll
            for (int mf = 0; mf < 2; ++mf) {
                uint32_t adr = buf + (uint32_t)(wm * 32 + mf * 16) * 80
                             + a_roff + kbyte + a_koff;
                LDSM4(A1f[mf], adr);
                LDSM4(A2f[mf], adr + TILE_BYTES);
            }
            uint32_t B1f[8][2], B2f[8][2];
#pragma unroll
            for (int nb = 0; nb < 4; ++nb) {
                uint32_t adr = buf + 2 * TILE_BYTES
                             + (uint32_t)(wn * 64 + nb * 16 + b_nloc) * 80
                             + kbyte + b_koff;
                uint32_t r[4];
                LDSM4(r, adr);
                B1f[nb*2][0] = r[0]; B1f[nb*2][1] = r[1];
                B1f[nb*2+1][0] = r[2]; B1f[nb*2+1][1] = r[3];
                LDSM4(r, adr + TILE_BYTES);
                B2f[nb*2][0] = r[0]; B2f[nb*2][1] = r[1];
                B2f[nb*2+1][0] = r[2]; B2f[nb*2+1][1] = r[3];
            }
#pragma unroll
            for (int mf = 0; mf < 2; ++mf)
#pragma unroll
                for (int nf = 0; nf < 8; ++nf) {
                    MMA_BF16(acc[mf][nf], A1f[mf], B1f[nf]);
                    MMA_BF16(acc[mf][nf], A1f[mf], B2f[nf]);
                    MMA_BF16(acc[mf][nf], A2f[mf], B1f[nf]);
                }
        }
        __syncthreads();
    }

    // ---- epilogue ----
    const int g = lane >> 2, tig = lane & 3;
    if (doRope) {
#pragma unroll
        for (int mf = 0; mf < 2; ++mf)
#pragma unroll
            for (int rh = 0; rh < 2; ++rh) {
                int row = m0 + wm*32 + mf*16 + g + rh*8;
                float tpos = (float)(row & (SEQ - 1));
                float* Crow = C + (size_t)row * DMODEL + n0 + wn*64;
#pragma unroll
                for (int nf = 0; nf < 4; ++nf) {
                    float o1[2], o2[2];
#pragma unroll
                    for (int b = 0; b < 2; ++b) {
                        int d = nf*8 + tig*2 + b;     // 0..31
                        float invf = exp2f(-(float)d * 0.4152410118609203f);
                        float th = tpos * invf;
                        float sn, cs;
                        sincosf(th, &sn, &cs);
                        float v1 = acc[mf][nf][rh*2 + b];
                        float v2 = acc[mf][nf+4][rh*2 + b];
                        o1[b] = v1*cs - v2*sn;
                        o2[b] = v2*cs + v1*sn;
                    }
                    *(float2*)(Crow + nf*8 + tig*2)      = make_float2(o1[0], o1[1]);
                    *(float2*)(Crow + nf*8 + tig*2 + 32) = make_float2(o2[0], o2[1]);
                }
            }
    } else {
#pragma unroll
        for (int mf = 0; mf < 2; ++mf)
#pragma unroll
            for (int rh = 0; rh < 2; ++rh) {
                int row = m0 + wm*32 + mf*16 + g + rh*8;
                float* Crow = C + (size_t)row * DMODEL + n0 + wn*64;
#pragma unroll
                for (int nf = 0; nf < 8; ++nf)
                    *(float2*)(Crow + nf*8 + tig*2) =
                        make_float2(acc[mf][nf][rh*2], acc[mf][nf][rh*2 + 1]);
            }
    }
}

// ---------------- flash attention (round-1, unchanged) ----------------------
#define ASTR 68
__global__ __launch_bounds__(256)
void attn_kernel()
{
    extern __shared__ __align__(16) float smf[];
    float* Qs = smf;
    float* Ks = smf + 64*ASTR;
    float* Vs = smf + 2*64*ASTR;
    float* Ps = smf + 3*64*ASTR;

    const int tid = threadIdx.x;
    const int tx  = tid & 15;
    const int ty  = tid >> 4;
    const int it  = blockIdx.x;
    const int h   = blockIdx.y;
    const int b   = blockIdx.z;
    const int i0  = it << 6;

    {
        int r  = tid >> 2;
        int c0 = (tid & 3) << 4;
        const float* qp = g_q + (size_t)(b*SEQ + i0 + r)*DMODEL + h*HD + c0;
#pragma unroll
        for (int u = 0; u < 4; ++u) {
            float4 v = *(const float4*)(qp + u*4);
            Qs[(c0 + u*4 + 0)*ASTR + r] = v.x;
            Qs[(c0 + u*4 + 1)*ASTR + r] = v.y;
            Qs[(c0 + u*4 + 2)*ASTR + r] = v.z;
            Qs[(c0 + u*4 + 3)*ASTR + r] = v.w;
        }
    }

    float m[4], l[4], o[4][4];
#pragma unroll
    for (int i = 0; i < 4; ++i) {
        m[i] = -3.0e38f; l[i] = 0.f;
#pragma unroll
        for (int j = 0; j < 4; ++j) o[i][j] = 0.f;
    }

    for (int jt = 0; jt <= it; ++jt) {
        const int j0 = jt << 6;
        int r  = tid >> 2;
        int c0 = (tid & 3) << 4;
        const float* kp = g_k + (size_t)(b*SEQ + j0 + r)*DMODEL + h*HD + c0;
        const float* vp = g_v + (size_t)(b*SEQ + j0 + r)*DMODEL + h*HD + c0;
        float4 kv[4], vv[4];
#pragma unroll
        for (int u = 0; u < 4; ++u) {
            kv[u] = *(const float4*)(kp + u*4);
            vv[u] = *(const float4*)(vp + u*4);
        }
        __syncthreads();
#pragma unroll
        for (int u = 0; u < 4; ++u) {
            Ks[(c0 + u*4 + 0)*ASTR + r] = kv[u].x;
            Ks[(c0 + u*4 + 1)*ASTR + r] = kv[u].y;
            Ks[(c0 + u*4 + 2)*ASTR + r] = kv[u].z;
            Ks[(c0 + u*4 + 3)*ASTR + r] = kv[u].w;
            *(float4*)(Vs + r*ASTR + c0 + u*4) = vv[u];
        }
        __syncthreads();

        float s[4][4];
#pragma unroll
        for (int i = 0; i < 4; ++i)
#pragma unroll
            for (int j = 0; j < 4; ++j) s[i][j] = 0.f;
#pragma unroll
        for (int k = 0; k < 64; ++k) {
            float4 a  = *(const float4*)(Qs + k*ASTR + ty*4);
            float4 bq = *(const float4*)(Ks + k*ASTR + tx*4);
            float aa[4] = {a.x, a.y, a.z, a.w};
            float bb[4] = {bq.x, bq.y, bq.z, bq.w};
#pragma unroll
            for (int i = 0; i < 4; ++i)
#pragma unroll
                for (int j = 0; j < 4; ++j)
                    s[i][j] = fmaf(aa[i], bb[j], s[i][j]);
        }
#pragma unroll
        for (int i = 0; i < 4; ++i)
#pragma unroll
            for (int j = 0; j < 4; ++j) s[i][j] *= ATT_SCALE;

        if (jt == it) {
#pragma unroll
            for (int i = 0; i < 4; ++i)
#pragma unroll
                for (int j = 0; j < 4; ++j)
                    if (j0 + tx*4 + j > i0 + ty*4 + i) s[i][j] = -1.0e30f;
        }

        float p[4][4];
#pragma unroll
        for (int i = 0; i < 4; ++i) {
            float tm = fmaxf(fmaxf(s[i][0], s[i][1]), fmaxf(s[i][2], s[i][3]));
#pragma unroll
            for (int off = 8; off >= 1; off >>= 1)
                tm = fmaxf(tm, __shfl_xor_sync(0xffffffffu, tm, off));
            float mnew = fmaxf(m[i], tm);
            float corr = expf(m[i] - mnew);
            float rs = 0.f;
#pragma unroll
            for (int j = 0; j < 4; ++j) {
                float e = expf(s[i][j] - mnew);
                p[i][j] = e;
                rs += e;
            }
#pragma unroll
            for (int off = 8; off >= 1; off >>= 1)
                rs += __shfl_xor_sync(0xffffffffu, rs, off);
            l[i] = l[i]*corr + rs;
            m[i] = mnew;
#pragma unroll
            for (int d = 0; d < 4; ++d) o[i][d] *= corr;
        }

#pragma unroll
        for (int j = 0; j < 4; ++j)
#pragma unroll
            for (int i = 0; i < 4; ++i)
                Ps[(tx*4 + j)*ASTR + ty*4 + i] = p[i][j];
        __syncthreads();

#pragma unroll
        for (int k = 0; k < 64; ++k) {
            float4 a  = *(const float4*)(Ps + k*ASTR + ty*4);
            float4 bv = *(const float4*)(Vs + k*ASTR + tx*4);
            float aa[4] = {a.x, a.y, a.z, a.w};
            float bb[4] = {bv.x, bv.y, bv.z, bv.w};
#pragma unroll
            for (int i = 0; i < 4; ++i)
#pragma unroll
                for (int d = 0; d < 4; ++d)
                    o[i][d] = fmaf(aa[i], bb[d], o[i][d]);
        }
    }

#pragma unroll
    for (int i = 0; i < 4; ++i) {
        float inv = 1.f / l[i];
        int row = i0 + ty*4 + i;
        float4 w = make_float4(o[i][0]*inv, o[i][1]*inv, o[i][2]*inv, o[i][3]*inv);
        *(float4*)(g_attn + (size_t)(b*SEQ + row)*DMODEL + h*HD + tx*4) = w;
    }
}

// ---------------------------------------------------------------------------
extern "C" void kernel_launch(void* const* d_in, const int* in_sizes, int n_in,
                              void* d_out, int out_size)
{
    const float* x  = (const float*)d_in[0];
    const float* wq = (const float*)d_in[1];
    const float* wk = (const float*)d_in[2];
    const float* wv = (const float*)d_in[3];
    const float* wo = (const float*)d_in[4];
    float* out = (float*)d_out;

    float *q, *k, *v, *attn;
    __nv_bfloat16 *xs1, *xs2, *as1, *as2, *w1, *w2;
    cudaGetSymbolAddress((void**)&q,    g_q);
    cudaGetSymbolAddress((void**)&k,    g_k);
    cudaGetSymbolAddress((void**)&v,    g_v);
    cudaGetSymbolAddress((void**)&attn, g_attn);
    cudaGetSymbolAddress((void**)&xs1,  g_xs1);
    cudaGetSymbolAddress((void**)&xs2,  g_xs2);
    cudaGetSymbolAddress((void**)&as1,  g_as1);
    cudaGetSymbolAddress((void**)&as2,  g_as2);
    cudaGetSymbolAddress((void**)&w1,   g_w1);
    cudaGetSymbolAddress((void**)&w2,   g_w2);

    const int WN = DMODEL * DMODEL;
    const int shm_gemm = 2 * STAGE_BYTES;    // 81920
    cudaFuncSetAttribute(gemm_mma, cudaFuncAttributeMaxDynamicSharedMemorySize, shm_gemm);

    split_kernel<<<(MTOT*DMODEL/4 + 255)/256, 256>>>(x, xs1, xs2, MTOT*DMODEL/4);
    split_kernel<<<(WN/4 + 255)/256, 256>>>(wq, w1 + 0*WN, w2 + 0*WN, WN/4);
    split_kernel<<<(WN/4 + 255)/256, 256>>>(wk, w1 + 1*WN, w2 + 1*WN, WN/4);
    split_kernel<<<(WN/4 + 255)/256, 256>>>(wv, w1 + 2*WN, w2 + 2*WN, WN/4);
    split_kernel<<<(WN/4 + 255)/256, 256>>>(wo, w1 + 3*WN, w2 + 3*WN, WN/4);

    dim3 gg(DMODEL/128, MTOT/128);   // (8, 32)
    gemm_mma<<<gg, 256, shm_gemm>>>(xs1, xs2, w1 + 0*WN, w2 + 0*WN, q, 1);
    gemm_mma<<<gg, 256, shm_gemm>>>(xs1, xs2, w1 + 1*WN, w2 + 1*WN, k, 1);
    gemm_mma<<<gg, 256, shm_gemm>>>(xs1, xs2, w1 + 2*WN, w2 + 2*WN, v, 0);

    size_t shm_attn = (size_t)4 * 64 * ASTR * sizeof(float);
    cudaFuncSetAttribute(attn_kernel, cudaFuncAttributeMaxDynamicSharedMemorySize, (int)shm_attn);
    attn_kernel<<<dim3(SEQ/64, NH, NB), 256, shm_attn>>>();

    split_kernel<<<(MTOT*DMODEL/4 + 255)/256, 256>>>(attn, as1, as2, MTOT*DMODEL/4);
    gemm_mma<<<gg, 256, shm_gemm>>>(as1, as2, w1 + 3*WN, w2 + 3*WN, out, 0);
}

// round 4
// speedup vs baseline: 2.8097x; 1.8885x over previous
#include <cuda_runtime.h>
#include <cuda_bf16.h>
#include <math.h>
#include <stdint.h>

#define DMODEL 1024
#define SEQ    2048
#define NB     2
#define NH     16
#define HD     64
#define MTOT   (NB*SEQ)          // 4096

// ---------------- scratch (__device__ globals; allocation-free rule) --------
__device__ __align__(16) __nv_bfloat16 g_xs1[MTOT*DMODEL];
__device__ __align__(16) __nv_bfloat16 g_xs2[MTOT*DMODEL];
__device__ __align__(16) __nv_bfloat16 g_as1[MTOT*DMODEL];
__device__ __align__(16) __nv_bfloat16 g_as2[MTOT*DMODEL];
__device__ __align__(16) __nv_bfloat16 g_w1[4*DMODEL*DMODEL];
__device__ __align__(16) __nv_bfloat16 g_w2[4*DMODEL*DMODEL];
__device__ __align__(16) __nv_bfloat16 g_q1[MTOT*DMODEL];
__device__ __align__(16) __nv_bfloat16 g_q2[MTOT*DMODEL];
__device__ __align__(16) __nv_bfloat16 g_k1[MTOT*DMODEL];
__device__ __align__(16) __nv_bfloat16 g_k2[MTOT*DMODEL];
__device__ __align__(16) __nv_bfloat16 g_v1[MTOT*DMODEL];
__device__ __align__(16) __nv_bfloat16 g_v2[MTOT*DMODEL];

// ---------------- PTX helpers ----------------------------------------------
__device__ __forceinline__ uint32_t smem_u32(const void* p) {
    uint32_t a;
    asm("{ .reg .u64 t; cvta.to.shared.u64 t, %1; cvt.u32.u64 %0, t; }"
        : "=r"(a) : "l"(p));
    return a;
}
__device__ __forceinline__ void cp16(uint32_t dst, const void* src) {
    asm volatile("cp.async.cg.shared.global [%0], [%1], 16;" :: "r"(dst), "l"(src));
}
#define CP_COMMIT()  asm volatile("cp.async.commit_group;" ::: "memory")
#define CP_WAIT(n)   asm volatile("cp.async.wait_group %0;" :: "n"(n) : "memory")

#define LDSM4(r, adr) \
    asm volatile("ldmatrix.sync.aligned.m8n8.x4.shared.b16 {%0,%1,%2,%3}, [%4];" \
        : "=r"((r)[0]), "=r"((r)[1]), "=r"((r)[2]), "=r"((r)[3]) : "r"(adr))
#define LDSM4T(r, adr) \
    asm volatile("ldmatrix.sync.aligned.m8n8.x4.trans.shared.b16 {%0,%1,%2,%3}, [%4];" \
        : "=r"((r)[0]), "=r"((r)[1]), "=r"((r)[2]), "=r"((r)[3]) : "r"(adr))

#define MMA_BF16(c, a, b) \
    asm volatile("mma.sync.aligned.m16n8k16.row.col.f32.bf16.bf16.f32 " \
        "{%0,%1,%2,%3}, {%4,%5,%6,%7}, {%8,%9}, {%0,%1,%2,%3};" \
        : "+f"((c)[0]), "+f"((c)[1]), "+f"((c)[2]), "+f"((c)[3]) \
        : "r"((a)[0]), "r"((a)[1]), "r"((a)[2]), "r"((a)[3]), \
          "r"((b)[0]), "r"((b)[1]))

// pack(lo=a, hi=b) as bf16x2
__device__ __forceinline__ uint32_t packbf(float a, float b) {
    uint32_t r;
    asm("cvt.rn.bf16x2.f32 %0, %1, %2;" : "=r"(r) : "f"(b), "f"(a));
    return r;
}
// split pair (a,b) -> hi bf16x2 + residual bf16x2
__device__ __forceinline__ void split2(float a, float b, uint32_t& hi, uint32_t& lo) {
    hi = packbf(a, b);
    float ah = __int_as_float(hi << 16);
    float bh = __int_as_float(hi & 0xffff0000u);
    lo = packbf(a - ah, b - bh);
}

// ---------------- split kernel: fp32 -> bf16 hi + bf16 lo -------------------
__global__ __launch_bounds__(256)
void split_kernel(const float* __restrict__ s, __nv_bfloat16* __restrict__ d1,
                  __nv_bfloat16* __restrict__ d2, int n4)
{
    int i = blockIdx.x * blockDim.x + threadIdx.x;
    if (i >= n4) return;
    float4 v = ((const float4*)s)[i];
    uint32_t h0, l0, h1, l1;
    split2(v.x, v.y, h0, l0);
    split2(v.z, v.w, h1, l1);
    ((uint2*)d1)[i] = make_uint2(h0, h1);
    ((uint2*)d2)[i] = make_uint2(l0, l1);
}

// ---------------- mma.sync GEMM: C[M,1024] = A @ W^T ------------------------
// mode 0: fp32 C. mode 1: RoPE + 0.125 scale -> split bf16 D1/D2 (Q).
// mode 2: RoPE -> split (K). mode 3: plain -> split (V).
#define TILE_BYTES 10240            // 128*40*2
#define STAGE_BYTES (4*TILE_BYTES)

__global__ __launch_bounds__(256)
void gemm_mma(const __nv_bfloat16* __restrict__ A1, const __nv_bfloat16* __restrict__ A2,
              const __nv_bfloat16* __restrict__ B1, const __nv_bfloat16* __restrict__ B2,
              float* __restrict__ C, __nv_bfloat16* __restrict__ D1,
              __nv_bfloat16* __restrict__ D2, int mode)
{
    extern __shared__ __align__(16) char sm[];
    const uint32_t sb = smem_u32(sm);
    const int tid = threadIdx.x;
    const int lane = tid & 31, wid = tid >> 5;
    const int wm = wid & 3, wn = wid >> 2;
    const int m0 = blockIdx.y << 7, n0 = blockIdx.x << 7;

    float acc[2][8][4];
#pragma unroll
    for (int mf = 0; mf < 2; ++mf)
#pragma unroll
        for (int nf = 0; nf < 8; ++nf)
#pragma unroll
            for (int j = 0; j < 4; ++j) acc[mf][nf][j] = 0.f;

    const int lrow0 = tid >> 2;
    const int lch   = tid & 3;

    auto load_stage = [&](int t) {
        const int k0 = t << 5;
        const uint32_t base = sb + (uint32_t)(t & 1) * STAGE_BYTES;
#pragma unroll
        for (int tile = 0; tile < 4; ++tile) {
            const __nv_bfloat16* S = (tile == 0) ? A1 : (tile == 1) ? A2
                                   : (tile == 2) ? B1 : B2;
            const int rb = (tile < 2) ? m0 : n0;
#pragma unroll
            for (int u = 0; u < 2; ++u) {
                int row = lrow0 + (u << 6);
                cp16(base + tile * TILE_BYTES + row * 80 + lch * 16,
                     S + (size_t)(rb + row) * DMODEL + k0 + lch * 8);
            }
        }
    };

    load_stage(0);
    CP_COMMIT();

    const uint32_t a_roff = (uint32_t)(lane & 15) * 80;
    const uint32_t a_koff = (uint32_t)(lane >> 4) * 16;
    const int      b_nloc = (lane & 7) + ((lane >> 4) & 1) * 8;
    const uint32_t b_koff = (uint32_t)((lane >> 3) & 1) * 16;

    for (int t = 0; t < 32; ++t) {
        if (t < 31) {
            load_stage(t + 1);
            CP_COMMIT();
            CP_WAIT(1);
        } else {
            CP_WAIT(0);
        }
        __syncthreads();

        const uint32_t buf = sb + (uint32_t)(t & 1) * STAGE_BYTES;
#pragma unroll
        for (int ks = 0; ks < 2; ++ks) {
            const uint32_t kbyte = (uint32_t)ks * 32;
            uint32_t A1f[2][4], A2f[2][4];
#pragma unroll
            for (int mf = 0; mf < 2; ++mf) {
                uint32_t adr = buf + (uint32_t)(wm * 32 + mf * 16) * 80
                             + a_roff + kbyte + a_koff;
                LDSM4(A1f[mf], adr);
                LDSM4(A2f[mf], adr + TILE_BYTES);
            }
            uint32_t B1f[8][2], B2f[8][2];
#pragma unroll
            for (int nb = 0; nb < 4; ++nb) {
                uint32_t adr = buf + 2 * TILE_BYTES
                             + (uint32_t)(wn * 64 + nb * 16 + b_nloc) * 80
                             + kbyte + b_koff;
                uint32_t r[4];
                LDSM4(r, adr);
                B1f[nb*2][0] = r[0]; B1f[nb*2][1] = r[1];
                B1f[nb*2+1][0] = r[2]; B1f[nb*2+1][1] = r[3];
                LDSM4(r, adr + TILE_BYTES);
                B2f[nb*2][0] = r[0]; B2f[nb*2][1] = r[1];
                B2f[nb*2+1][0] = r[2]; B2f[nb*2+1][1] = r[3];
            }
#pragma unroll
            for (int mf = 0; mf < 2; ++mf)
#pragma unroll
                for (int nf = 0; nf < 8; ++nf) {
                    MMA_BF16(acc[mf][nf], A1f[mf], B1f[nf]);
                    MMA_BF16(acc[mf][nf], A1f[mf], B2f[nf]);
                    MMA_BF16(acc[mf][nf], A2f[mf], B1f[nf]);
                }
        }
        __syncthreads();
    }

    // ---- epilogue ----
    const int g = lane >> 2, tg = lane & 3;
    if (mode == 1 || mode == 2) {
        const float sc = (mode == 1) ? 0.125f : 1.0f;
#pragma unroll
        for (int mf = 0; mf < 2; ++mf)
#pragma unroll
            for (int rh = 0; rh < 2; ++rh) {
                int row = m0 + wm*32 + mf*16 + g + rh*8;
                float tpos = (float)(row & (SEQ - 1));
                size_t base = (size_t)row * DMODEL + n0 + wn*64;
#pragma unroll
                for (int nf = 0; nf < 4; ++nf) {
                    float o1[2], o2[2];
#pragma unroll
                    for (int bb = 0; bb < 2; ++bb) {
                        int d = nf*8 + tg*2 + bb;
                        float invf = exp2f(-(float)d * 0.4152410118609203f);
                        float th = tpos * invf;
                        float sn, cs;
                        sincosf(th, &sn, &cs);
                        float v1 = acc[mf][nf][rh*2 + bb];
                        float v2 = acc[mf][nf+4][rh*2 + bb];
                        o1[bb] = (v1*cs - v2*sn) * sc;
                        o2[bb] = (v2*cs + v1*sn) * sc;
                    }
                    uint32_t h_, l_;
                    split2(o1[0], o1[1], h_, l_);
                    *(uint32_t*)(D1 + base + nf*8 + tg*2) = h_;
                    *(uint32_t*)(D2 + base + nf*8 + tg*2) = l_;
                    split2(o2[0], o2[1], h_, l_);
                    *(uint32_t*)(D1 + base + nf*8 + tg*2 + 32) = h_;
                    *(uint32_t*)(D2 + base + nf*8 + tg*2 + 32) = l_;
                }
            }
    } else if (mode == 3) {
#pragma unroll
        for (int mf = 0; mf < 2; ++mf)
#pragma unroll
            for (int rh = 0; rh < 2; ++rh) {
                int row = m0 + wm*32 + mf*16 + g + rh*8;
                size_t base = (size_t)row * DMODEL + n0 + wn*64;
#pragma unroll
                for (int nf = 0; nf < 8; ++nf) {
                    uint32_t h_, l_;
                    split2(acc[mf][nf][rh*2], acc[mf][nf][rh*2+1], h_, l_);
                    *(uint32_t*)(D1 + base + nf*8 + tg*2) = h_;
                    *(uint32_t*)(D2 + base + nf*8 + tg*2) = l_;
                }
            }
    } else {
#pragma unroll
        for (int mf = 0; mf < 2; ++mf)
#pragma unroll
            for (int rh = 0; rh < 2; ++rh) {
                int row = m0 + wm*32 + mf*16 + g + rh*8;
                float* Crow = C + (size_t)row * DMODEL + n0 + wn*64;
#pragma unroll
                for (int nf = 0; nf < 8; ++nf)
                    *(float2*)(Crow + nf*8 + tg*2) =
                        make_float2(acc[mf][nf][rh*2], acc[mf][nf][rh*2 + 1]);
            }
    }
}

// ---------------- tensor-core flash attention -------------------------------
// CTA = 64 q rows of one (b,h); 4 warps x 16 rows; KV tiles of 64, causal.
// smem rows padded to 144B (72 bf16) => conflict-free ldmatrix.
#define ROWB 144
#define TB   (64*ROWB)      // 9216 per tensor tile
#define STG  (4*TB)         // K1,K2,V1,V2 per stage

__global__ __launch_bounds__(128)
void attn_mma()
{
    extern __shared__ __align__(16) char sm[];
    const uint32_t sb = smem_u32(sm);
    const int tid = threadIdx.x, lane = tid & 31, w = tid >> 5;
    const int it = gridDim.x - 1 - blockIdx.x;      // long CTAs first
    const int h = blockIdx.y, b = blockIdx.z;
    const int i0 = it << 6;
    const size_t hoff = (size_t)h * HD;
    const int g = lane >> 2, tg = lane & 3;

    // ---- stage Q through stage-0 K slots ----
#pragma unroll
    for (int p = 0; p < 4; ++p) {
        int id = tid + (p << 7);
        int row = id >> 3, ch = id & 7;
        size_t gi = (size_t)(b*SEQ + i0 + row)*DMODEL + hoff + ch*8;
        uint32_t dst = sb + row*ROWB + ch*16;
        cp16(dst,      g_q1 + gi);
        cp16(dst + TB, g_q2 + gi);
    }
    CP_COMMIT(); CP_WAIT(0); __syncthreads();

    uint32_t Q1f[4][4], Q2f[4][4];
    const uint32_t a_off = (uint32_t)(lane & 15)*ROWB + (uint32_t)(lane >> 4)*16;
#pragma unroll
    for (int kf = 0; kf < 4; ++kf) {
        uint32_t adr = sb + (uint32_t)(w*16)*ROWB + a_off + kf*32;
        LDSM4(Q1f[kf], adr);
        LDSM4(Q2f[kf], adr + TB);
    }
    __syncthreads();

    auto load_kv = [&](int jt) {
        const int j0 = jt << 6;
        const uint32_t base = sb + (uint32_t)(jt & 1)*STG;
#pragma unroll
        for (int p = 0; p < 4; ++p) {
            int id = tid + (p << 7);
            int row = id >> 3, ch = id & 7;
            size_t gi = (size_t)(b*SEQ + j0 + row)*DMODEL + hoff + ch*8;
            uint32_t dst = base + row*ROWB + ch*16;
            cp16(dst,        g_k1 + gi);
            cp16(dst + TB,   g_k2 + gi);
            cp16(dst + 2*TB, g_v1 + gi);
            cp16(dst + 3*TB, g_v2 + gi);
        }
    };

    load_kv(0); CP_COMMIT();

    float mr[2] = {-1e30f, -1e30f}, lr[2] = {0.f, 0.f};
    float O[8][4];
#pragma unroll
    for (int nf = 0; nf < 8; ++nf)
#pragma unroll
        for (int j = 0; j < 4; ++j) O[nf][j] = 0.f;

    const int      b_nloc = (lane & 7) + ((lane >> 4) & 1)*8;
    const uint32_t b_koff = (uint32_t)((lane >> 3) & 1)*16;

    for (int jt = 0; jt <= it; ++jt) {
        if (jt < it) { load_kv(jt + 1); CP_COMMIT(); CP_WAIT(1); }
        else         { CP_WAIT(0); }
        __syncthreads();
        const uint32_t buf = sb + (uint32_t)(jt & 1)*STG;

        // ---- S = Q K^T (3-term split) ----
        float S[8][4];
#pragma unroll
        for (int nf = 0; nf < 8; ++nf)
#pragma unroll
            for (int j = 0; j < 4; ++j) S[nf][j] = 0.f;

#pragma unroll
        for (int kf = 0; kf < 4; ++kf) {
            uint32_t K1f[8][2], K2f[8][2];
#pragma unroll
            for (int nb = 0; nb < 4; ++nb) {
                uint32_t adr = buf + (uint32_t)(nb*16 + b_nloc)*ROWB + kf*32 + b_koff;
                uint32_t r[4];
                LDSM4(r, adr);
                K1f[2*nb][0] = r[0]; K1f[2*nb][1] = r[1];
                K1f[2*nb+1][0] = r[2]; K1f[2*nb+1][1] = r[3];
                LDSM4(r, adr + TB);
                K2f[2*nb][0] = r[0]; K2f[2*nb][1] = r[1];
                K2f[2*nb+1][0] = r[2]; K2f[2*nb+1][1] = r[3];
            }
#pragma unroll
            for (int nf = 0; nf < 8; ++nf) {
                MMA_BF16(S[nf], Q1f[kf], K1f[nf]);
                MMA_BF16(S[nf], Q1f[kf], K2f[nf]);
                MMA_BF16(S[nf], Q2f[kf], K1f[nf]);
            }
        }

        // ---- causal mask (diagonal tile only; tiles are 64/64 aligned) ----
        if (jt == it) {
            int r0 = w*16 + g;
#pragma unroll
            for (int nf = 0; nf < 8; ++nf)
#pragma unroll
                for (int j = 0; j < 2; ++j) {
                    int col = nf*8 + tg*2 + j;
                    if (col > r0)     S[nf][j]   = -1e30f;
                    if (col > r0 + 8) S[nf][j+2] = -1e30f;
                }
        }

        // ---- online softmax ----
        float mx0 = -1e30f, mx1 = -1e30f;
#pragma unroll
        for (int nf = 0; nf < 8; ++nf) {
            mx0 = fmaxf(mx0, fmaxf(S[nf][0], S[nf][1]));
            mx1 = fmaxf(mx1, fmaxf(S[nf][2], S[nf][3]));
        }
        mx0 = fmaxf(mx0, __shfl_xor_sync(0xffffffffu, mx0, 1));
        mx0 = fmaxf(mx0, __shfl_xor_sync(0xffffffffu, mx0, 2));
        mx1 = fmaxf(mx1, __shfl_xor_sync(0xffffffffu, mx1, 1));
        mx1 = fmaxf(mx1, __shfl_xor_sync(0xffffffffu, mx1, 2));
        float mn0 = fmaxf(mr[0], mx0), mn1 = fmaxf(mr[1], mx1);
        float c0 = __expf(mr[0] - mn0), c1 = __expf(mr[1] - mn1);
        float s0 = 0.f, s1 = 0.f;
#pragma unroll
        for (int nf = 0; nf < 8; ++nf) {
            S[nf][0] = __expf(S[nf][0] - mn0);
            S[nf][1] = __expf(S[nf][1] - mn0);
            S[nf][2] = __expf(S[nf][2] - mn1);
            S[nf][3] = __expf(S[nf][3] - mn1);
            s0 += S[nf][0] + S[nf][1];
            s1 += S[nf][2] + S[nf][3];
        }
        s0 += __shfl_xor_sync(0xffffffffu, s0, 1);
        s0 += __shfl_xor_sync(0xffffffffu, s0, 2);
        s1 += __shfl_xor_sync(0xffffffffu, s1, 1);
        s1 += __shfl_xor_sync(0xffffffffu, s1, 2);
        lr[0] = lr[0]*c0 + s0;  lr[1] = lr[1]*c1 + s1;
        mr[0] = mn0;            mr[1] = mn1;
#pragma unroll
        for (int nf = 0; nf < 8; ++nf) {
            O[nf][0] *= c0; O[nf][1] *= c0;
            O[nf][2] *= c1; O[nf][3] *= c1;
        }

        // ---- O += P V (P in registers, split; V via ldmatrix.trans) ----
#pragma unroll
        for (int kg = 0; kg < 4; ++kg) {
            uint32_t P1a[4], P2a[4];
            split2(S[2*kg][0],   S[2*kg][1],   P1a[0], P2a[0]);
            split2(S[2*kg][2],   S[2*kg][3],   P1a[1], P2a[1]);
            split2(S[2*kg+1][0], S[2*kg+1][1], P1a[2], P2a[2]);
            split2(S[2*kg+1][2], S[2*kg+1][3], P1a[3], P2a[3]);
            const uint32_t vrow = buf + 2*TB
                                + (uint32_t)(kg*16 + (lane & 15))*ROWB
                                + (uint32_t)(lane >> 4)*16;
#pragma unroll
            for (int np = 0; np < 4; ++np) {
                uint32_t v1[4], v2[4];
                LDSM4T(v1, vrow + np*32);
                LDSM4T(v2, vrow + np*32 + TB);
                uint32_t bA[2] = {v1[0], v1[1]}, bB[2] = {v1[2], v1[3]};
                uint32_t cA[2] = {v2[0], v2[1]}, cB[2] = {v2[2], v2[3]};
                MMA_BF16(O[2*np],   P1a, bA);
                MMA_BF16(O[2*np],   P1a, cA);
                MMA_BF16(O[2*np],   P2a, bA);
                MMA_BF16(O[2*np+1], P1a, bB);
                MMA_BF16(O[2*np+1], P1a, cB);
                MMA_BF16(O[2*np+1], P2a, bB);
            }
        }
        __syncthreads();   // compute done before next stage overwrite
    }

    // ---- epilogue: normalize, split bf16, feed Wo GEMM directly ----
    float inv0 = 1.f / lr[0], inv1 = 1.f / lr[1];
    int r0 = i0 + w*16 + g;
    size_t base0 = (size_t)(b*SEQ + r0)    *DMODEL + hoff + tg*2;
    size_t base1 = (size_t)(b*SEQ + r0 + 8)*DMODEL + hoff + tg*2;
#pragma unroll
    for (int nf = 0; nf < 8; ++nf) {
        uint32_t h_, l_;
        split2(O[nf][0]*inv0, O[nf][1]*inv0, h_, l_);
        *(uint32_t*)(g_as1 + base0 + nf*8) = h_;
        *(uint32_t*)(g_as2 + base0 + nf*8) = l_;
        split2(O[nf][2]*inv1, O[nf][3]*inv1, h_, l_);
        *(uint32_t*)(g_as1 + base1 + nf*8) = h_;
        *(uint32_t*)(g_as2 + base1 + nf*8) = l_;
    }
}

// ---------------------------------------------------------------------------
extern "C" void kernel_launch(void* const* d_in, const int* in_sizes, int n_in,
                              void* d_out, int out_size)
{
    const float* x  = (const float*)d_in[0];
    const float* wq = (const float*)d_in[1];
    const float* wk = (const float*)d_in[2];
    const float* wv = (const float*)d_in[3];
    const float* wo = (const float*)d_in[4];
    float* out = (float*)d_out;

    __nv_bfloat16 *xs1, *xs2, *as1, *as2, *w1, *w2;
    __nv_bfloat16 *q1, *q2, *k1, *k2, *v1, *v2;
    cudaGetSymbolAddress((void**)&xs1, g_xs1);
    cudaGetSymbolAddress((void**)&xs2, g_xs2);
    cudaGetSymbolAddress((void**)&as1, g_as1);
    cudaGetSymbolAddress((void**)&as2, g_as2);
    cudaGetSymbolAddress((void**)&w1,  g_w1);
    cudaGetSymbolAddress((void**)&w2,  g_w2);
    cudaGetSymbolAddress((void**)&q1,  g_q1);
    cudaGetSymbolAddress((void**)&q2,  g_q2);
    cudaGetSymbolAddress((void**)&k1,  g_k1);
    cudaGetSymbolAddress((void**)&k2,  g_k2);
    cudaGetSymbolAddress((void**)&v1,  g_v1);
    cudaGetSymbolAddress((void**)&v2,  g_v2);

    const int WN = DMODEL * DMODEL;
    const int shm_gemm = 2 * STAGE_BYTES;
    cudaFuncSetAttribute(gemm_mma, cudaFuncAttributeMaxDynamicSharedMemorySize, shm_gemm);

    split_kernel<<<(MTOT*DMODEL/4 + 255)/256, 256>>>(x, xs1, xs2, MTOT*DMODEL/4);
    split_kernel<<<(WN/4 + 255)/256, 256>>>(wq, w1 + 0*WN, w2 + 0*WN, WN/4);
    split_kernel<<<(WN/4 + 255)/256, 256>>>(wk, w1 + 1*WN, w2 + 1*WN, WN/4);
    split_kernel<<<(WN/4 + 255)/256, 256>>>(wv, w1 + 2*WN, w2 + 2*WN, WN/4);
    split_kernel<<<(WN/4 + 255)/256, 256>>>(wo, w1 + 3*WN, w2 + 3*WN, WN/4);

    dim3 gg(DMODEL/128, MTOT/128);
    gemm_mma<<<gg, 256, shm_gemm>>>(xs1, xs2, w1 + 0*WN, w2 + 0*WN, nullptr, q1, q2, 1);
    gemm_mma<<<gg, 256, shm_gemm>>>(xs1, xs2, w1 + 1*WN, w2 + 1*WN, nullptr, k1, k2, 2);
    gemm_mma<<<gg, 256, shm_gemm>>>(xs1, xs2, w1 + 2*WN, w2 + 2*WN, nullptr, v1, v2, 3);

    const int shm_attn = 2 * STG;   // 73728
    cudaFuncSetAttribute(attn_mma, cudaFuncAttributeMaxDynamicSharedMemorySize, shm_attn);
    attn_mma<<<dim3(SEQ/64, NH, NB), 128, shm_attn>>>();

    gemm_mma<<<gg, 256, shm_gemm>>>(as1, as2, w1 + 3*WN, w2 + 3*WN, out, nullptr, nullptr, 0);
}